// round 8
// baseline (speedup 1.0000x reference)
#include <cuda_runtime.h>
#include <math.h>

#define HOP      160
#define NFFT     512
#define WINLEN   320
#define NMELS    80
#define NBINS    257
#define PREEMPH  0.97f
#define LOG_EPSF 5.9604644775390625e-08f   /* 2^-24 */
#define STD_EPSF 1e-5f
#define BLANKF   27.0f

#define WTAPS    32                 /* padded taps per mel row */
#define FPB      8                  /* frames per block (8 warps = 4 pair-FFTs) */
#define PB_PITCH 268                /* pbuf[frame][bin] pitch: 67x16B -> conflict-free LDS.128 */
#define YBUF     ((FPB - 1) * HOP + NFFT)   /* 1632 */

/* static smem (floats):
 * tw    512      (256 float2)
 * A:    4096     zsh (4 pairs x 1024)  OVERLAYS ybuf(1632)+wwin(512)
 * pbuf  8*268
 */
#define SM_A_FLOATS 4096

__device__ __align__(16) float g_mw[NMELS * WTAPS];
__device__ int    g_mstart[NMELS];
__device__ float2 g_tw[NFFT / 2];
__device__ float  g_win[NFFT];

/* xn may be int32 (JAX default) or int64; lengths >= 160000 so word[1]==0
 * implies int64 layout. Only in-bounds words are read either way. */
__device__ __forceinline__ int load_seqlen(const int* __restrict__ xn32, int b) {
    int is64 = (xn32[1] == 0);
    int v = is64 ? xn32[2 * b] : xn32[b];
    return v / HOP + 1;
}

/* ------------------------------------------------------------------ K0 */
__global__ void k_tables(const float* __restrict__ fb) {
    const int m   = blockIdx.x;
    const int tid = threadIdx.x;   /* 64 */

    if (m == NMELS) {
        for (int i = tid; i < NFFT / 2; i += 64) {
            float s, c;
            sincosf((float)i * (-6.283185307179586f / 512.0f), &s, &c);
            g_tw[i] = make_float2(c, s);
        }
        return;
    }
    if (m == NMELS + 1) {
        for (int i = tid; i < NFFT; i += 64) {
            float w = 0.0f;
            if (i >= (NFFT - WINLEN) / 2 && i < (NFFT + WINLEN) / 2) {
                float ph = (float)(i - (NFFT - WINLEN) / 2) *
                           (6.283185307179586f / (float)WINLEN);
                w = 0.5f - 0.5f * cosf(ph);
            }
            g_win[i] = w;
        }
        return;
    }

    __shared__ int sf0, sf1;
    if (tid == 0) { sf0 = NBINS; sf1 = -1; }
    __syncthreads();

    const float* row = fb + m * NBINS;
    int f0 = NBINS, f1 = -1;
    for (int k = tid; k < NBINS; k += 64) {
        if (row[k] != 0.0f) { if (k < f0) f0 = k; if (k > f1) f1 = k; }
    }
    atomicMin(&sf0, f0);
    atomicMax(&sf1, f1);
    __syncthreads();
    f0 = sf0; f1 = sf1;
    if (f1 < 0) { f0 = 0; f1 = 0; }

    int s4 = f0 & ~3;
    if (s4 > NBINS - WTAPS + 3) s4 = (NBINS - WTAPS + 3) & ~3;   /* 228 */
    if (tid == 0) g_mstart[m] = s4;
    for (int j = tid; j < WTAPS; j += 64) {
        int k = s4 + j;
        g_mw[m * WTAPS + j] = (k >= f0 && k <= f1 && k < NBINS) ? row[k] : 0.0f;
    }
}

/* ------------------------------------------------------------------ K1:
 * fused preemph + reflect + window + pair-FFT (2 warps/pair, 8 pts/thread)
 * + sparse mel. 256 threads, 8 warps, 8 frames/block.
 */
__global__ void __launch_bounds__(256, 4)
k_fftmel(const float* __restrict__ x, float* __restrict__ out,
         int L, int T, int Tpad) {
    __shared__ float2 tw[NFFT / 2];
    __shared__ float  smA[SM_A_FLOATS];
    __shared__ float  pbuf[FPB * PB_PITCH];

    float* ybuf = smA;                 /* [0,1632)  */
    float* wwin = smA + YBUF;          /* [1632,2144) */

    const int tid   = threadIdx.x;
    const int w     = tid >> 5;
    const int t     = tid & 31;
    const int wp    = w >> 1;          /* pair 0..3  */
    const int hw    = w & 1;           /* half 0..1  */
    const int b     = blockIdx.y;
    const int tbase = blockIdx.x * FPB;

    tw[tid] = g_tw[tid];
    wwin[tid]       = g_win[tid];
    wwin[tid + 256] = g_win[tid + 256];

    /* zero mel-tap tail bins (257..259) for all 8 frames */
    if (tid < FPB * 3) {
        int f = tid / 3;
        pbuf[f * PB_PITCH + NBINS + (tid - f * 3)] = 0.0f;
    }

    /* stage preemphasized, reflect-padded span */
    const float* xb = x + (size_t)b * L;
    const int jbase = tbase * HOP - NFFT / 2;
    for (int i = tid; i < YBUF; i += 256) {
        int j = jbase + i;
        int jj = (j < 0) ? -j : ((j >= L) ? (2 * L - 2 - j) : j);
        ybuf[i] = (jj == 0) ? xb[0] : (xb[jj] - PREEMPH * xb[jj - 1]);
    }
    __syncthreads();

    const int t0   = tbase + 2 * wp;
    const bool has0 = (t0 < T);
    const bool has1 = (t0 + 1 < T);
    const int base = 2 * wp * HOP;

    /* windowed load + stage 0 (h=256): warp keeps its half */
    float Rr[8], Ri[8];
    #pragma unroll
    for (int q = 0; q < 8; q++) {
        int iL = q * 32 + t;
        int iU = iL + 256;
        float wL = wwin[iL], wU = wwin[iU];
        float Lre = has0 ? ybuf[base + iL] * wL : 0.0f;
        float Lim = has1 ? ybuf[base + HOP + iL] * wL : 0.0f;
        float Ure = has0 ? ybuf[base + iU] * wU : 0.0f;
        float Uim = has1 ? ybuf[base + HOP + iU] * wU : 0.0f;
        if (hw == 0) {
            Rr[q] = Lre + Ure;
            Ri[q] = Lim + Uim;
        } else {
            float2 c = tw[iL];
            float dr = Lre - Ure, di = Lim - Uim;
            Rr[q] = dr * c.x - di * c.y;
            Ri[q] = dr * c.y + di * c.x;
        }
    }
    /* registers hold everything; zsh may overwrite ybuf/wwin */
    __syncthreads();

    /* per-warp 256-pt FFT.  j = q*32 + t.
     * stages h=128,64,32: in-thread (partner q^(h/32)), twidx = (j&(h-1))*(256/h) */
    #pragma unroll
    for (int s = 1; s < 4; s++) {
        const int h  = 256 >> s;       /* 128,64,32 */
        const int qh = h >> 5;         /* 4,2,1 */
        #pragma unroll
        for (int qb = 0; qb < 8; qb++) {
            if (!(qb & qh)) {
                const int q1 = qb + qh;
                int p = ((qb & (qh - 1)) * 32 + t);
                float2 c = tw[p << s];
                float ur = Rr[qb], ui = Ri[qb];
                float vr = Rr[q1], vi = Ri[q1];
                float dr = ur - vr, di = ui - vi;
                Rr[qb] = ur + vr;  Ri[qb] = ui + vi;
                Rr[q1] = dr * c.x - di * c.y;
                Ri[q1] = dr * c.y + di * c.x;
            }
        }
    }

    /* stages h=16,8,4,2,1: cross-lane shfl_xor, twiddle lane-only */
    #pragma unroll
    for (int s = 4; s < 9; s++) {
        const int hh = 256 >> s;       /* 16,8,4,2,1 */
        float2 c = tw[(t & (hh - 1)) << s];
        const bool up = (t & hh) != 0;
        #pragma unroll
        for (int q = 0; q < 8; q++) {
            float pr = __shfl_xor_sync(0xffffffffu, Rr[q], hh);
            float pi = __shfl_xor_sync(0xffffffffu, Ri[q], hh);
            if (!up) {
                Rr[q] += pr;  Ri[q] += pi;
            } else {
                float dr = pr - Rr[q], di = pi - Ri[q];
                Rr[q] = dr * c.x - di * c.y;
                Ri[q] = dr * c.y + di * c.x;
            }
        }
    }

    /* dump to pair strip (layout identical to single-warp version) */
    float* zr = smA + wp * 1024;
    float* zi = zr + 512;
    #pragma unroll
    for (int q = 0; q < 8; q++) {
        zr[hw * 256 + q * 32 + t] = Rr[q];
        zi[hw * 256 + q * 32 + t] = Ri[q];
    }
    __syncthreads();

    /* unpack packed real pair -> power rows (frames 2wp, 2wp+1) */
    for (int k = t + 32 * hw; k <= NFFT / 2; k += 64) {
        int kn = (NFFT - k) & (NFFT - 1);
        int r1 = __brev(k)  >> 23;
        int r2 = __brev(kn) >> 23;
        float z1r = zr[r1], z1i = zi[r1];
        float z2r = zr[r2], z2i = zi[r2];
        float Ar = 0.5f * (z1r + z2r);
        float Ai = 0.5f * (z1i - z2i);
        float Br = 0.5f * (z1i + z2i);
        float Bi = 0.5f * (z2r - z1r);
        pbuf[(2 * wp) * PB_PITCH + k]     = Ar * Ar + Ai * Ai;
        pbuf[(2 * wp + 1) * PB_PITCH + k] = Br * Br + Bi * Bi;
    }
    __syncthreads();

    /* sparse mel + log: 640 outputs (80 mels x 8 frames), vectorized taps */
    for (int oi = tid; oi < NMELS * FPB; oi += 256) {
        int m    = oi >> 3;
        int tloc = oi & 7;
        int s4   = g_mstart[m];
        const float4* wm = (const float4*)(g_mw + m * WTAPS);
        const float4* pv = (const float4*)(pbuf + tloc * PB_PITCH + s4);
        float acc = 0.0f;
        #pragma unroll
        for (int j = 0; j < WTAPS / 4; j++) {
            float4 f = __ldg(&wm[j]);
            float4 p = pv[j];
            acc += f.x * p.x + f.y * p.y + f.z * p.z + f.w * p.w;
        }
        int tt = tbase + tloc;
        if (tt < T)
            out[((size_t)b * NMELS + m) * Tpad + tt] = __logf(acc + LOG_EPSF);
    }
}

/* ------------------------------------------------------------------ K2:
 * per-(b,m) single-pass masked mean/var normalization, float4, in-place.
 * Block (m==0) thread 0 also writes batch b's seq_len tail entry.
 */
__global__ void k_norm(float* __restrict__ out, const int* __restrict__ xn32,
                       int T, int Tpad, size_t mainElems, int rem, int B) {
    __shared__ float rsum[8], rsq[8];

    const int tid  = threadIdx.x;          /* 256 */
    const int lane = tid & 31;
    const int wid  = tid >> 5;
    const int m    = blockIdx.x;
    const int b    = blockIdx.y;

    const int seq = load_seqlen(xn32, b);
    int n = seq;
    if (n < 2) n = 2;
    if (n > T) n = T;

    if (m == 0 && tid == 0 && rem > 0) {
        if (rem == B) {
            out[mainElems + b] = (float)seq;
        } else if (rem == 2 * B) {
            ((long long*)(out + mainElems))[b] = (long long)seq;
        } else if (b == 0) {
            for (int i = 0; i < rem && i < B; i++)
                out[mainElems + i] = (float)load_seqlen(xn32, i);
        }
    }

    float* row = out + ((size_t)b * NMELS + m) * Tpad;
    float4* row4 = (float4*)row;
    const int nq = (n + 3) >> 2;

    float lsum = 0.0f, lsq = 0.0f;
    for (int i4 = tid; i4 < nq; i4 += 256) {
        float4 v = row4[i4];
        int tb = 4 * i4;
        if (tb + 0 < n) { lsum += v.x; lsq += v.x * v.x; }
        if (tb + 1 < n) { lsum += v.y; lsq += v.y * v.y; }
        if (tb + 2 < n) { lsum += v.z; lsq += v.z * v.z; }
        if (tb + 3 < n) { lsum += v.w; lsq += v.w * v.w; }
    }
    #pragma unroll
    for (int o = 16; o > 0; o >>= 1) {
        lsum += __shfl_xor_sync(0xffffffffu, lsum, o);
        lsq  += __shfl_xor_sync(0xffffffffu, lsq, o);
    }
    if (lane == 0) { rsum[wid] = lsum; rsq[wid] = lsq; }
    __syncthreads();
    float s1 = rsum[lane & 7], s2 = rsq[lane & 7];
    #pragma unroll
    for (int o = 4; o > 0; o >>= 1) {
        s1 += __shfl_xor_sync(0xffffffffu, s1, o);
        s2 += __shfl_xor_sync(0xffffffffu, s2, o);
    }
    s1 = __shfl_sync(0xffffffffu, s1, 0);
    s2 = __shfl_sync(0xffffffffu, s2, 0);

    const float fn   = (float)n;
    const float mean = s1 / fn;
    const float var  = (s2 - fn * mean * mean) / (fn - 1.0f);
    const float inv  = 1.0f / (sqrtf(fmaxf(var, 0.0f)) + STD_EPSF);

    const int tq = Tpad >> 2;
    for (int i4 = tid; i4 < tq; i4 += 256) {
        float4 v = row4[i4];
        int tb = 4 * i4;
        float4 o;
        o.x = (tb + 0 < n) ? (v.x - mean) * inv : ((tb + 0 < T) ? 0.0f : BLANKF);
        o.y = (tb + 1 < n) ? (v.y - mean) * inv : ((tb + 1 < T) ? 0.0f : BLANKF);
        o.z = (tb + 2 < n) ? (v.z - mean) * inv : ((tb + 2 < T) ? 0.0f : BLANKF);
        o.w = (tb + 3 < n) ? (v.w - mean) * inv : ((tb + 3 < T) ? 0.0f : BLANKF);
        row4[i4] = o;
    }
}

extern "C" void kernel_launch(void* const* d_in, const int* in_sizes, int n_in,
                              void* d_out, int out_size) {
    const float* x    = (const float*)d_in[0];
    const int*   xn32 = (const int*)d_in[1];
    const float* fb   = (const float*)d_in[2];

    const int B    = in_sizes[1];
    const int L    = in_sizes[0] / B;
    const int T    = L / HOP + 1;
    const int Tpad = ((T + 7) / 8) * 8;

    float* out = (float*)d_out;

    k_tables<<<NMELS + 2, 64>>>(fb);
    k_fftmel<<<dim3((T + FPB - 1) / FPB, B), 256>>>(x, out, L, T, Tpad);

    size_t mainE = (size_t)B * NMELS * Tpad;
    int rem = out_size - (int)mainE;
    k_norm<<<dim3(NMELS, B), 256>>>(out, xn32, T, Tpad, mainE, rem, B);
}

// round 9
// speedup vs baseline: 1.1155x; 1.1155x over previous
#include <cuda_runtime.h>
#include <math.h>

#define HOP      160
#define NFFT     512
#define WINLEN   320
#define NMELS    80
#define NBINS    257
#define PREEMPH  0.97f
#define LOG_EPSF 5.9604644775390625e-08f   /* 2^-24 */
#define STD_EPSF 1e-5f
#define BLANKF   27.0f

#define WTAPS    32                 /* padded taps per mel row */
#define FPB      16                 /* frames per block (8 warps x 1 pair) */
#define PB_PITCH 268                /* pbuf[frame][bin] pitch: 67x16B -> conflict-free LDS.128 */
#define YBUF     ((FPB - 1) * HOP + NFFT)   /* 2912 samples staged per block */

/* dynamic smem (floats), zsh overlays ybuf+wwin (disjoint lifetimes):
 * [0,512)          tw    (256 float2)
 * [512,8704)       A:    zsh (8 warps x 1024)  OVERLAYS  ybuf(2912)+wwin(512)
 * [8704,12992)     pbuf  (16*268) [frame][bin]
 */
#define SM_TW    0
#define SM_A     512
#define SM_YBUF  SM_A
#define SM_WWIN  (SM_A + YBUF)
#define SM_PBUF  (SM_A + 8 * 1024)
#define SM_FLOATS (SM_PBUF + FPB * PB_PITCH)
#define SMEM_BYTES (SM_FLOATS * 4)          /* 51968 B */

__device__ __align__(16) float g_mw[NMELS * WTAPS];
__device__ int    g_mstart[NMELS];
__device__ float2 g_tw[NFFT / 2];
__device__ float  g_win[NFFT];

/* xn may be int32 (JAX default) or int64; lengths >= 160000 so word[1]==0
 * implies int64 layout. Only in-bounds words are read either way. */
__device__ __forceinline__ int load_seqlen(const int* __restrict__ xn32, int b) {
    int is64 = (xn32[1] == 0);
    int v = is64 ? xn32[2 * b] : xn32[b];
    return v / HOP + 1;
}

/* ------------------------------------------------------------------ K0 */
__global__ void k_tables(const float* __restrict__ fb) {
    const int m   = blockIdx.x;
    const int tid = threadIdx.x;   /* 64 */

    if (m == NMELS) {
        for (int i = tid; i < NFFT / 2; i += 64) {
            float s, c;
            sincosf((float)i * (-6.283185307179586f / 512.0f), &s, &c);
            g_tw[i] = make_float2(c, s);
        }
        return;
    }
    if (m == NMELS + 1) {
        for (int i = tid; i < NFFT; i += 64) {
            float w = 0.0f;
            if (i >= (NFFT - WINLEN) / 2 && i < (NFFT + WINLEN) / 2) {
                float ph = (float)(i - (NFFT - WINLEN) / 2) *
                           (6.283185307179586f / (float)WINLEN);
                w = 0.5f - 0.5f * cosf(ph);
            }
            g_win[i] = w;
        }
        return;
    }

    __shared__ int sf0, sf1;
    if (tid == 0) { sf0 = NBINS; sf1 = -1; }
    __syncthreads();

    const float* row = fb + m * NBINS;
    int f0 = NBINS, f1 = -1;
    for (int k = tid; k < NBINS; k += 64) {
        if (row[k] != 0.0f) { if (k < f0) f0 = k; if (k > f1) f1 = k; }
    }
    atomicMin(&sf0, f0);
    atomicMax(&sf1, f1);
    __syncthreads();
    f0 = sf0; f1 = sf1;
    if (f1 < 0) { f0 = 0; f1 = 0; }

    int s4 = f0 & ~3;
    if (s4 > NBINS - WTAPS + 3) s4 = (NBINS - WTAPS + 3) & ~3;   /* 228 */
    if (tid == 0) g_mstart[m] = s4;
    for (int j = tid; j < WTAPS; j += 64) {
        int k = s4 + j;
        g_mw[m * WTAPS + j] = (k >= f0 && k <= f1 && k < NBINS) ? row[k] : 0.0f;
    }
}

/* ------------------------------------------------------------------ K1:
 * fused preemph + reflect + window + warp-register pair-FFT + sparse mel.
 * 256 threads, 8 warps, 16 frames per block; one pair-FFT per warp,
 * each thread holds 16 complex points in registers.
 */
__global__ void __launch_bounds__(256, 3)
k_fftmel(const float* __restrict__ x, float* __restrict__ out,
         int L, int T, int Tpad) {
    extern __shared__ float sm[];
    float2* tw  = (float2*)(sm + SM_TW);
    float* ybuf = sm + SM_YBUF;
    float* wwin = sm + SM_WWIN;
    float* pbuf = sm + SM_PBUF;

    const int tid   = threadIdx.x;
    const int w     = tid >> 5;
    const int t     = tid & 31;
    const int b     = blockIdx.y;
    const int tbase = blockIdx.x * FPB;

    /* tables to smem */
    tw[tid] = g_tw[tid];
    wwin[tid]       = g_win[tid];
    wwin[tid + 256] = g_win[tid + 256];

    /* zero mel-tap tail bins (257..259) for all 16 frames */
    if (tid < FPB * 3) {
        int f = tid / 3;
        pbuf[f * PB_PITCH + NBINS + (tid - f * 3)] = 0.0f;
    }

    /* stage preemphasized, reflect-padded span */
    const float* xb = x + (size_t)b * L;
    const int jbase = tbase * HOP - NFFT / 2;
    for (int i = tid; i < YBUF; i += 256) {
        int j = jbase + i;
        int jj = (j < 0) ? -j : ((j >= L) ? (2 * L - 2 - j) : j);
        ybuf[i] = (jj == 0) ? xb[0] : (xb[jj] - PREEMPH * xb[jj - 1]);
    }
    __syncthreads();

    const int t0   = tbase + 2 * w;
    const bool has0 = (t0 < T);
    const bool has1 = (t0 + 1 < T);

    float Rr[16], Ri[16];
    const int base = 2 * w * HOP;
    #pragma unroll
    for (int q = 0; q < 16; q++) {
        int i = q * 32 + t;
        float wv = wwin[i];
        Rr[q] = has0 ? ybuf[base + i] * wv : 0.0f;
        Ri[q] = has1 ? ybuf[base + HOP + i] * wv : 0.0f;
    }
    /* all frames now in registers; zsh may overwrite ybuf/wwin */
    __syncthreads();

    /* stages 0..3: within-thread butterflies (partner is another q) */
    #pragma unroll
    for (int s = 0; s < 4; s++) {
        const int qh = 8 >> s;
        #pragma unroll
        for (int qb = 0; qb < 16; qb++) {
            if (!(qb & qh)) {
                const int q1 = qb + qh;
                int idx = (((qb & (qh - 1)) * 32 + t) << s);
                float2 c = tw[idx];
                float ur = Rr[qb], ui = Ri[qb];
                float vr = Rr[q1], vi = Ri[q1];
                float dr = ur - vr, di = ui - vi;
                Rr[qb] = ur + vr;  Ri[qb] = ui + vi;
                Rr[q1] = dr * c.x - di * c.y;
                Ri[q1] = dr * c.y + di * c.x;
            }
        }
    }

    /* stages 4..8: cross-lane via shfl_xor; twiddle depends only on lane */
    #pragma unroll
    for (int s = 4; s < 9; s++) {
        const int hh = 256 >> s;           /* 16,8,4,2,1 */
        float2 c = tw[(t & (hh - 1)) << s];
        const bool up = (t & hh) != 0;
        #pragma unroll
        for (int q = 0; q < 16; q++) {
            float pr = __shfl_xor_sync(0xffffffffu, Rr[q], hh);
            float pi = __shfl_xor_sync(0xffffffffu, Ri[q], hh);
            if (!up) {
                Rr[q] += pr;  Ri[q] += pi;
            } else {
                float dr = pr - Rr[q], di = pi - Ri[q];
                Rr[q] = dr * c.x - di * c.y;
                Ri[q] = dr * c.y + di * c.x;
            }
        }
    }

    /* dump bit-reversed-position data to this warp's smem strip */
    float* zr = sm + SM_A + w * 1024;
    float* zi = zr + 512;
    #pragma unroll
    for (int q = 0; q < 16; q++) {
        zr[q * 32 + t] = Rr[q];
        zi[q * 32 + t] = Ri[q];
    }
    __syncwarp();

    /* unpack packed real pair -> power rows (frames 2w, 2w+1) */
    for (int k = t; k <= NFFT / 2; k += 32) {
        int kn = (NFFT - k) & (NFFT - 1);
        int r1 = __brev(k)  >> 23;
        int r2 = __brev(kn) >> 23;
        float z1r = zr[r1], z1i = zi[r1];
        float z2r = zr[r2], z2i = zi[r2];
        float Ar = 0.5f * (z1r + z2r);
        float Ai = 0.5f * (z1i - z2i);
        float Br = 0.5f * (z1i + z2i);
        float Bi = 0.5f * (z2r - z1r);
        pbuf[(2 * w) * PB_PITCH + k]     = Ar * Ar + Ai * Ai;
        pbuf[(2 * w + 1) * PB_PITCH + k] = Br * Br + Bi * Bi;
    }
    __syncthreads();

    /* sparse mel + log: 1280 outputs (80 mels x 16 frames), vectorized taps */
    for (int oi = tid; oi < NMELS * FPB; oi += 256) {
        int m    = oi >> 4;
        int tloc = oi & 15;
        int s4   = g_mstart[m];
        const float4* wm = (const float4*)(g_mw + m * WTAPS);
        const float4* pv = (const float4*)(pbuf + tloc * PB_PITCH + s4);
        float acc = 0.0f;
        #pragma unroll
        for (int j = 0; j < WTAPS / 4; j++) {
            float4 f = __ldg(&wm[j]);
            float4 p = pv[j];
            acc += f.x * p.x + f.y * p.y + f.z * p.z + f.w * p.w;
        }
        int tt = tbase + tloc;
        if (tt < T)
            out[((size_t)b * NMELS + m) * Tpad + tt] = __logf(acc + LOG_EPSF);
    }
}

/* ------------------------------------------------------------------ K2:
 * per-(b,m) single-pass masked mean/var normalization, float4, in-place.
 * Block (m==0) thread 0 also writes batch b's seq_len tail entry.
 */
__global__ void k_norm(float* __restrict__ out, const int* __restrict__ xn32,
                       int T, int Tpad, size_t mainElems, int rem, int B) {
    __shared__ float rsum[8], rsq[8];

    const int tid  = threadIdx.x;          /* 256 */
    const int lane = tid & 31;
    const int wid  = tid >> 5;
    const int m    = blockIdx.x;
    const int b    = blockIdx.y;

    const int seq = load_seqlen(xn32, b);
    int n = seq;
    if (n < 2) n = 2;
    if (n > T) n = T;

    if (m == 0 && tid == 0 && rem > 0) {
        if (rem == B) {
            out[mainElems + b] = (float)seq;
        } else if (rem == 2 * B) {
            ((long long*)(out + mainElems))[b] = (long long)seq;
        } else if (b == 0) {
            for (int i = 0; i < rem && i < B; i++)
                out[mainElems + i] = (float)load_seqlen(xn32, i);
        }
    }

    float* row = out + ((size_t)b * NMELS + m) * Tpad;
    float4* row4 = (float4*)row;
    const int nq = (n + 3) >> 2;

    float lsum = 0.0f, lsq = 0.0f;
    for (int i4 = tid; i4 < nq; i4 += 256) {
        float4 v = row4[i4];
        int tb = 4 * i4;
        if (tb + 0 < n) { lsum += v.x; lsq += v.x * v.x; }
        if (tb + 1 < n) { lsum += v.y; lsq += v.y * v.y; }
        if (tb + 2 < n) { lsum += v.z; lsq += v.z * v.z; }
        if (tb + 3 < n) { lsum += v.w; lsq += v.w * v.w; }
    }
    #pragma unroll
    for (int o = 16; o > 0; o >>= 1) {
        lsum += __shfl_xor_sync(0xffffffffu, lsum, o);
        lsq  += __shfl_xor_sync(0xffffffffu, lsq, o);
    }
    if (lane == 0) { rsum[wid] = lsum; rsq[wid] = lsq; }
    __syncthreads();
    float s1 = rsum[lane & 7], s2 = rsq[lane & 7];
    #pragma unroll
    for (int o = 4; o > 0; o >>= 1) {
        s1 += __shfl_xor_sync(0xffffffffu, s1, o);
        s2 += __shfl_xor_sync(0xffffffffu, s2, o);
    }
    s1 = __shfl_sync(0xffffffffu, s1, 0);
    s2 = __shfl_sync(0xffffffffu, s2, 0);

    const float fn   = (float)n;
    const float mean = s1 / fn;
    const float var  = (s2 - fn * mean * mean) / (fn - 1.0f);
    const float inv  = 1.0f / (sqrtf(fmaxf(var, 0.0f)) + STD_EPSF);

    const int tq = Tpad >> 2;
    for (int i4 = tid; i4 < tq; i4 += 256) {
        float4 v = row4[i4];
        int tb = 4 * i4;
        float4 o;
        o.x = (tb + 0 < n) ? (v.x - mean) * inv : ((tb + 0 < T) ? 0.0f : BLANKF);
        o.y = (tb + 1 < n) ? (v.y - mean) * inv : ((tb + 1 < T) ? 0.0f : BLANKF);
        o.z = (tb + 2 < n) ? (v.z - mean) * inv : ((tb + 2 < T) ? 0.0f : BLANKF);
        o.w = (tb + 3 < n) ? (v.w - mean) * inv : ((tb + 3 < T) ? 0.0f : BLANKF);
        row4[i4] = o;
    }
}

extern "C" void kernel_launch(void* const* d_in, const int* in_sizes, int n_in,
                              void* d_out, int out_size) {
    const float* x    = (const float*)d_in[0];
    const int*   xn32 = (const int*)d_in[1];
    const float* fb   = (const float*)d_in[2];

    const int B    = in_sizes[1];
    const int L    = in_sizes[0] / B;
    const int T    = L / HOP + 1;
    const int Tpad = ((T + 7) / 8) * 8;

    float* out = (float*)d_out;

    cudaFuncSetAttribute(k_fftmel, cudaFuncAttributeMaxDynamicSharedMemorySize,
                         SMEM_BYTES);

    k_tables<<<NMELS + 2, 64>>>(fb);
    k_fftmel<<<dim3((T + FPB - 1) / FPB, B), 256, SMEM_BYTES>>>(x, out, L, T, Tpad);

    size_t mainE = (size_t)B * NMELS * Tpad;
    int rem = out_size - (int)mainE;
    k_norm<<<dim3(NMELS, B), 256>>>(out, xn32, T, Tpad, mainE, rem, B);
}

// round 10
// speedup vs baseline: 1.2070x; 1.0821x over previous
#include <cuda_runtime.h>
#include <math.h>

#define HOP      160
#define NFFT     512
#define WINLEN   320
#define NMELS    80
#define NBINS    257
#define PREEMPH  0.97f
#define LOG_EPSF 5.9604644775390625e-08f   /* 2^-24 */
#define STD_EPSF 1e-5f
#define BLANKF   27.0f

#define WTAPS    32                 /* padded taps per mel row (storage) */
#define FPB      16                 /* frames per block (8 warps x 1 pair) */
#define PB_PITCH 268                /* pbuf[frame][bin] pitch: 67x16B -> conflict-free LDS.128 */
#define YBUF     ((FPB - 1) * HOP + NFFT)   /* 2912 samples staged per block */

/* dynamic smem (floats), zsh overlays ybuf+wwin (disjoint lifetimes):
 * [0,512)          tw    (256 float2)
 * [512,8704)       A:    zsh (8 warps x 1024)  OVERLAYS  ybuf(2912)+wwin(512)
 * [8704,12992)     pbuf  (16*268) [frame][bin]
 */
#define SM_TW    0
#define SM_A     512
#define SM_YBUF  SM_A
#define SM_WWIN  (SM_A + YBUF)
#define SM_PBUF  (SM_A + 8 * 1024)
#define SM_FLOATS (SM_PBUF + FPB * PB_PITCH)
#define SMEM_BYTES (SM_FLOATS * 4)          /* 51968 B */

__device__ __align__(16) float g_mw[NMELS * WTAPS];
__device__ int    g_mstart[NMELS];
__device__ int    g_mnq[NMELS];              /* live quads per mel (1..8) */
__device__ float2 g_tw[NFFT / 2];
__device__ float  g_win[NFFT];

/* xn may be int32 (JAX default) or int64; lengths >= 160000 so word[1]==0
 * implies int64 layout. Only in-bounds words are read either way. */
__device__ __forceinline__ int load_seqlen(const int* __restrict__ xn32, int b) {
    int is64 = (xn32[1] == 0);
    int v = is64 ? xn32[2 * b] : xn32[b];
    return v / HOP + 1;
}

/* ------------------------------------------------------------------ K0 */
__global__ void k_tables(const float* __restrict__ fb) {
    const int m   = blockIdx.x;
    const int tid = threadIdx.x;   /* 64 */

    if (m == NMELS) {
        for (int i = tid; i < NFFT / 2; i += 64) {
            float s, c;
            sincosf((float)i * (-6.283185307179586f / 512.0f), &s, &c);
            g_tw[i] = make_float2(c, s);
        }
        return;
    }
    if (m == NMELS + 1) {
        for (int i = tid; i < NFFT; i += 64) {
            float w = 0.0f;
            if (i >= (NFFT - WINLEN) / 2 && i < (NFFT + WINLEN) / 2) {
                float ph = (float)(i - (NFFT - WINLEN) / 2) *
                           (6.283185307179586f / (float)WINLEN);
                w = 0.5f - 0.5f * cosf(ph);
            }
            g_win[i] = w;
        }
        return;
    }

    __shared__ int sf0, sf1;
    if (tid == 0) { sf0 = NBINS; sf1 = -1; }
    __syncthreads();

    const float* row = fb + m * NBINS;
    int f0 = NBINS, f1 = -1;
    for (int k = tid; k < NBINS; k += 64) {
        if (row[k] != 0.0f) { if (k < f0) f0 = k; if (k > f1) f1 = k; }
    }
    atomicMin(&sf0, f0);
    atomicMax(&sf1, f1);
    __syncthreads();
    f0 = sf0; f1 = sf1;
    if (f1 < 0) { f0 = 0; f1 = 0; }

    int s4 = f0 & ~3;
    if (s4 > NBINS - WTAPS + 3) s4 = (NBINS - WTAPS + 3) & ~3;   /* 228 */
    if (tid == 0) {
        g_mstart[m] = s4;
        int nq = (f1 - s4 + 4) >> 2;        /* ceil((f1-s4+1)/4) */
        if (nq < 1) nq = 1;
        if (nq > WTAPS / 4) nq = WTAPS / 4;
        g_mnq[m] = nq;
    }
    for (int j = tid; j < WTAPS; j += 64) {
        int k = s4 + j;
        g_mw[m * WTAPS + j] = (k >= f0 && k <= f1 && k < NBINS) ? row[k] : 0.0f;
    }
}

/* ------------------------------------------------------------------ K1:
 * fused preemph + reflect + window + warp-register pair-FFT + sparse mel.
 * 256 threads, 8 warps, 16 frames per block; one pair-FFT per warp,
 * each thread holds 16 complex points in registers.
 */
__global__ void __launch_bounds__(256, 3)
k_fftmel(const float* __restrict__ x, float* __restrict__ out,
         int L, int T, int Tpad) {
    extern __shared__ float sm[];
    float2* tw  = (float2*)(sm + SM_TW);
    float* ybuf = sm + SM_YBUF;
    float* wwin = sm + SM_WWIN;
    float* pbuf = sm + SM_PBUF;

    const int tid   = threadIdx.x;
    const int w     = tid >> 5;
    const int t     = tid & 31;
    const int b     = blockIdx.y;
    const int tbase = blockIdx.x * FPB;

    /* tables to smem */
    tw[tid] = g_tw[tid];
    wwin[tid]       = g_win[tid];
    wwin[tid + 256] = g_win[tid + 256];

    /* zero mel-tap tail bins (257..259) for all 16 frames */
    if (tid < FPB * 3) {
        int f = tid / 3;
        pbuf[f * PB_PITCH + NBINS + (tid - f * 3)] = 0.0f;
    }

    /* stage preemphasized, reflect-padded span */
    const float* xb = x + (size_t)b * L;
    const int jbase = tbase * HOP - NFFT / 2;
    for (int i = tid; i < YBUF; i += 256) {
        int j = jbase + i;
        int jj = (j < 0) ? -j : ((j >= L) ? (2 * L - 2 - j) : j);
        ybuf[i] = (jj == 0) ? xb[0] : (xb[jj] - PREEMPH * xb[jj - 1]);
    }
    __syncthreads();

    const int t0   = tbase + 2 * w;
    const bool has0 = (t0 < T);
    const bool has1 = (t0 + 1 < T);

    float Rr[16], Ri[16];
    const int base = 2 * w * HOP;
    #pragma unroll
    for (int q = 0; q < 16; q++) {
        int i = q * 32 + t;
        float wv = wwin[i];
        Rr[q] = has0 ? ybuf[base + i] * wv : 0.0f;
        Ri[q] = has1 ? ybuf[base + HOP + i] * wv : 0.0f;
    }
    /* all frames now in registers; zsh may overwrite ybuf/wwin */
    __syncthreads();

    /* stages 0..3: within-thread butterflies (partner is another q) */
    #pragma unroll
    for (int s = 0; s < 4; s++) {
        const int qh = 8 >> s;
        #pragma unroll
        for (int qb = 0; qb < 16; qb++) {
            if (!(qb & qh)) {
                const int q1 = qb + qh;
                int idx = (((qb & (qh - 1)) * 32 + t) << s);
                float2 c = tw[idx];
                float ur = Rr[qb], ui = Ri[qb];
                float vr = Rr[q1], vi = Ri[q1];
                float dr = ur - vr, di = ui - vi;
                Rr[qb] = ur + vr;  Ri[qb] = ui + vi;
                Rr[q1] = dr * c.x - di * c.y;
                Ri[q1] = dr * c.y + di * c.x;
            }
        }
    }

    /* stages 4..8: cross-lane via shfl_xor; twiddle depends only on lane */
    #pragma unroll
    for (int s = 4; s < 9; s++) {
        const int hh = 256 >> s;           /* 16,8,4,2,1 */
        float2 c = tw[(t & (hh - 1)) << s];
        const bool up = (t & hh) != 0;
        #pragma unroll
        for (int q = 0; q < 16; q++) {
            float pr = __shfl_xor_sync(0xffffffffu, Rr[q], hh);
            float pi = __shfl_xor_sync(0xffffffffu, Ri[q], hh);
            if (!up) {
                Rr[q] += pr;  Ri[q] += pi;
            } else {
                float dr = pr - Rr[q], di = pi - Ri[q];
                Rr[q] = dr * c.x - di * c.y;
                Ri[q] = dr * c.y + di * c.x;
            }
        }
    }

    /* dump bit-reversed-position data to this warp's smem strip */
    float* zr = sm + SM_A + w * 1024;
    float* zi = zr + 512;
    #pragma unroll
    for (int q = 0; q < 16; q++) {
        zr[q * 32 + t] = Rr[q];
        zi[q * 32 + t] = Ri[q];
    }
    __syncwarp();

    /* unpack packed real pair -> power rows (frames 2w, 2w+1) */
    for (int k = t; k <= NFFT / 2; k += 32) {
        int kn = (NFFT - k) & (NFFT - 1);
        int r1 = __brev(k)  >> 23;
        int r2 = __brev(kn) >> 23;
        float z1r = zr[r1], z1i = zi[r1];
        float z2r = zr[r2], z2i = zi[r2];
        float Ar = 0.5f * (z1r + z2r);
        float Ai = 0.5f * (z1i - z2i);
        float Br = 0.5f * (z1i + z2i);
        float Bi = 0.5f * (z2r - z1r);
        pbuf[(2 * w) * PB_PITCH + k]     = Ar * Ar + Ai * Ai;
        pbuf[(2 * w + 1) * PB_PITCH + k] = Br * Br + Bi * Bi;
    }
    __syncthreads();

    /* sparse mel + log: 1280 outputs (80 mels x 16 frames),
     * variable-length vectorized taps (avg ~2-3 quads instead of 8) */
    for (int oi = tid; oi < NMELS * FPB; oi += 256) {
        int m    = oi >> 4;
        int tloc = oi & 15;
        int s4   = g_mstart[m];
        int nq   = g_mnq[m];
        const float4* wm = (const float4*)(g_mw + m * WTAPS);
        const float4* pv = (const float4*)(pbuf + tloc * PB_PITCH + s4);
        float acc = 0.0f;
        for (int j = 0; j < nq; j++) {
            float4 f = __ldg(&wm[j]);
            float4 p = pv[j];
            acc += f.x * p.x + f.y * p.y + f.z * p.z + f.w * p.w;
        }
        int tt = tbase + tloc;
        if (tt < T)
            out[((size_t)b * NMELS + m) * Tpad + tt] = __logf(acc + LOG_EPSF);
    }
}

/* ------------------------------------------------------------------ K2:
 * per-(b,m) single-pass masked mean/var normalization, float4, in-place.
 * Block (m==0) thread 0 also writes batch b's seq_len tail entry.
 */
__global__ void k_norm(float* __restrict__ out, const int* __restrict__ xn32,
                       int T, int Tpad, size_t mainElems, int rem, int B) {
    __shared__ float rsum[8], rsq[8];

    const int tid  = threadIdx.x;          /* 256 */
    const int lane = tid & 31;
    const int wid  = tid >> 5;
    const int m    = blockIdx.x;
    const int b    = blockIdx.y;

    const int seq = load_seqlen(xn32, b);
    int n = seq;
    if (n < 2) n = 2;
    if (n > T) n = T;

    if (m == 0 && tid == 0 && rem > 0) {
        if (rem == B) {
            out[mainElems + b] = (float)seq;
        } else if (rem == 2 * B) {
            ((long long*)(out + mainElems))[b] = (long long)seq;
        } else if (b == 0) {
            for (int i = 0; i < rem && i < B; i++)
                out[mainElems + i] = (float)load_seqlen(xn32, i);
        }
    }

    float* row = out + ((size_t)b * NMELS + m) * Tpad;
    float4* row4 = (float4*)row;
    const int nq = (n + 3) >> 2;

    float lsum = 0.0f, lsq = 0.0f;
    for (int i4 = tid; i4 < nq; i4 += 256) {
        float4 v = row4[i4];
        int tb = 4 * i4;
        if (tb + 0 < n) { lsum += v.x; lsq += v.x * v.x; }
        if (tb + 1 < n) { lsum += v.y; lsq += v.y * v.y; }
        if (tb + 2 < n) { lsum += v.z; lsq += v.z * v.z; }
        if (tb + 3 < n) { lsum += v.w; lsq += v.w * v.w; }
    }
    #pragma unroll
    for (int o = 16; o > 0; o >>= 1) {
        lsum += __shfl_xor_sync(0xffffffffu, lsum, o);
        lsq  += __shfl_xor_sync(0xffffffffu, lsq, o);
    }
    if (lane == 0) { rsum[wid] = lsum; rsq[wid] = lsq; }
    __syncthreads();
    float s1 = rsum[lane & 7], s2 = rsq[lane & 7];
    #pragma unroll
    for (int o = 4; o > 0; o >>= 1) {
        s1 += __shfl_xor_sync(0xffffffffu, s1, o);
        s2 += __shfl_xor_sync(0xffffffffu, s2, o);
    }
    s1 = __shfl_sync(0xffffffffu, s1, 0);
    s2 = __shfl_sync(0xffffffffu, s2, 0);

    const float fn   = (float)n;
    const float mean = s1 / fn;
    const float var  = (s2 - fn * mean * mean) / (fn - 1.0f);
    const float inv  = 1.0f / (sqrtf(fmaxf(var, 0.0f)) + STD_EPSF);

    const int tq = Tpad >> 2;
    for (int i4 = tid; i4 < tq; i4 += 256) {
        float4 v = row4[i4];
        int tb = 4 * i4;
        float4 o;
        o.x = (tb + 0 < n) ? (v.x - mean) * inv : ((tb + 0 < T) ? 0.0f : BLANKF);
        o.y = (tb + 1 < n) ? (v.y - mean) * inv : ((tb + 1 < T) ? 0.0f : BLANKF);
        o.z = (tb + 2 < n) ? (v.z - mean) * inv : ((tb + 2 < T) ? 0.0f : BLANKF);
        o.w = (tb + 3 < n) ? (v.w - mean) * inv : ((tb + 3 < T) ? 0.0f : BLANKF);
        row4[i4] = o;
    }
}

extern "C" void kernel_launch(void* const* d_in, const int* in_sizes, int n_in,
                              void* d_out, int out_size) {
    const float* x    = (const float*)d_in[0];
    const int*   xn32 = (const int*)d_in[1];
    const float* fb   = (const float*)d_in[2];

    const int B    = in_sizes[1];
    const int L    = in_sizes[0] / B;
    const int T    = L / HOP + 1;
    const int Tpad = ((T + 7) / 8) * 8;

    float* out = (float*)d_out;

    cudaFuncSetAttribute(k_fftmel, cudaFuncAttributeMaxDynamicSharedMemorySize,
                         SMEM_BYTES);

    k_tables<<<NMELS + 2, 64>>>(fb);
    k_fftmel<<<dim3((T + FPB - 1) / FPB, B), 256, SMEM_BYTES>>>(x, out, L, T, Tpad);

    size_t mainE = (size_t)B * NMELS * Tpad;
    int rem = out_size - (int)mainE;
    k_norm<<<dim3(NMELS, B), 256>>>(out, xn32, T, Tpad, mainE, rem, B);
}

// round 11
// speedup vs baseline: 1.8434x; 1.5272x over previous
#include <cuda_runtime.h>
#include <math.h>

#define HOP      160
#define NFFT     512
#define WINLEN   320
#define NMELS    80
#define NBINS    257
#define PREEMPH  0.97f
#define LOG_EPSF 5.9604644775390625e-08f   /* 2^-24 */
#define STD_EPSF 1e-5f
#define BLANKF   27.0f

#define WTAPS    32                 /* padded taps per mel row (storage) */
#define FPB      16                 /* frames per block (8 warps x 1 pair) */
#define PB_PITCH 268                /* pbuf[frame][bin] pitch */
#define YBUF     ((FPB - 1) * HOP + NFFT)   /* 2912 */
#define ZSTRIP   1056               /* per-warp zr(528)+zi(528), padded */

/* smem (floats):
 * [0,512)        tw (256 float2)
 * [512,8960)     A: zsh (8 x 1056)  OVERLAYS ybuf(2912)+wwin(512)
 * [8960,13248)   pbuf (16*268)
 */
#define SM_TW    0
#define SM_A     512
#define SM_YBUF  SM_A
#define SM_WWIN  (SM_A + YBUF)
#define SM_PBUF  (SM_A + 8 * ZSTRIP)
#define SM_FLOATS (SM_PBUF + FPB * PB_PITCH)
#define SMEM_BYTES (SM_FLOATS * 4)          /* 52992 B */

#define ZPAD(a) ((a) + ((a) >> 5))

__device__ __align__(16) float g_mw[NMELS * WTAPS];
__device__ int g_mstart[NMELS];
__device__ int g_mnq[NMELS];
__device__ int g_mel_ready;          /* zero-init; set once, idempotent */

/* xn may be int32 (JAX default) or int64; lengths >= 160000 so word[1]==0
 * implies int64 layout. Only in-bounds words are read either way. */
__device__ __forceinline__ int load_seqlen(const int* __restrict__ xn32, int b) {
    int is64 = (xn32[1] == 0);
    int v = is64 ? xn32[2 * b] : xn32[b];
    return v / HOP + 1;
}

/* ------------------------------------------------------------------ K1:
 * fused preemph + reflect + window + warp-register pair-FFT + sparse mel.
 * Block (0,0) additionally builds the sparse mel tables and releases a flag;
 * all blocks spin (cheaply, late) before the mel phase.
 */
__global__ void __launch_bounds__(256, 3)
k_fftmel(const float* __restrict__ x, const float* __restrict__ fb,
         float* __restrict__ out, int L, int T, int Tpad) {
    extern __shared__ float sm[];
    float2* tw  = (float2*)(sm + SM_TW);
    float* ybuf = sm + SM_YBUF;
    float* wwin = sm + SM_WWIN;
    float* pbuf = sm + SM_PBUF;

    const int tid   = threadIdx.x;
    const int w     = tid >> 5;
    const int t     = tid & 31;
    const int b     = blockIdx.y;
    const int tbase = blockIdx.x * FPB;
    const bool tblk = (blockIdx.x | blockIdx.y) == 0;

    /* ---- block (0,0): build mel tables, release flag ---- */
    if (tblk) {
        if (tid < NMELS) {
            const float* row = fb + tid * NBINS;
            int f0 = -1, f1 = 0;
            for (int k = 0; k < NBINS; k++) {
                float v = row[k];
                if (v != 0.0f) { if (f0 < 0) f0 = k; f1 = k; }
            }
            if (f0 < 0) { f0 = 0; f1 = 0; }
            int s4 = f0 & ~3;
            if (s4 > NBINS - WTAPS + 3) s4 = (NBINS - WTAPS + 3) & ~3;  /* 228 */
            g_mstart[tid] = s4;
            int nq = (f1 - s4 + 4) >> 2;
            if (nq < 1) nq = 1;
            if (nq > WTAPS / 4) nq = WTAPS / 4;
            g_mnq[tid] = nq;
            for (int j = 0; j < WTAPS; j++) {
                int k = s4 + j;
                g_mw[tid * WTAPS + j] =
                    (k >= f0 && k <= f1 && k < NBINS) ? row[k] : 0.0f;
            }
        }
        __syncthreads();
        if (tid == 0) { __threadfence(); atomicExch(&g_mel_ready, 1); }
    }

    /* ---- per-block tables via fast intrinsics ---- */
    {
        float s, c;
        __sincosf((float)tid * (-6.283185307179586f / 512.0f), &s, &c);
        tw[tid] = make_float2(c, s);
    }
    for (int i = tid; i < NFFT; i += 256) {
        float wv = 0.0f;
        if (i >= (NFFT - WINLEN) / 2 && i < (NFFT + WINLEN) / 2)
            wv = 0.5f - 0.5f * __cosf((float)(i - (NFFT - WINLEN) / 2) *
                                      (6.283185307179586f / (float)WINLEN));
        wwin[i] = wv;
    }

    /* zero mel-tap tail bins (257..267) for all 16 frames */
    for (int i = tid; i < FPB * (PB_PITCH - NBINS); i += 256) {
        int f = i / (PB_PITCH - NBINS);
        pbuf[f * PB_PITCH + NBINS + (i - f * (PB_PITCH - NBINS))] = 0.0f;
    }

    /* ---- stage preemphasized, reflect-padded span ---- */
    const float* xb = x + (size_t)b * L;
    const int jbase = tbase * HOP - NFFT / 2;
    if (jbase >= 1 && jbase + YBUF <= L) {
        /* interior: vectorized preemph, no reflection */
        const float4* xv = (const float4*)(xb + jbase);
        for (int i4 = tid; i4 < YBUF / 4; i4 += 256) {
            float4 v = xv[i4];
            float xm1 = xb[jbase + 4 * i4 - 1];
            float4 o;
            o.x = v.x - PREEMPH * xm1;
            o.y = v.y - PREEMPH * v.x;
            o.z = v.z - PREEMPH * v.y;
            o.w = v.w - PREEMPH * v.z;
            *(float4*)(ybuf + 4 * i4) = o;
        }
    } else {
        for (int i = tid; i < YBUF; i += 256) {
            int j = jbase + i;
            int jj = (j < 0) ? -j : ((j >= L) ? (2 * L - 2 - j) : j);
            ybuf[i] = (jj == 0) ? xb[0] : (xb[jj] - PREEMPH * xb[jj - 1]);
        }
    }
    __syncthreads();

    const int t0   = tbase + 2 * w;
    const bool has0 = (t0 < T);
    const bool has1 = (t0 + 1 < T);

    float Rr[16], Ri[16];
    const int base = 2 * w * HOP;
    #pragma unroll
    for (int q = 0; q < 16; q++) {
        int i = q * 32 + t;
        float wv = wwin[i];
        Rr[q] = has0 ? ybuf[base + i] * wv : 0.0f;
        Ri[q] = has1 ? ybuf[base + HOP + i] * wv : 0.0f;
    }
    /* all frames in registers; zsh may overwrite ybuf/wwin */
    __syncthreads();

    /* stages 0..3: within-thread butterflies */
    #pragma unroll
    for (int s = 0; s < 4; s++) {
        const int qh = 8 >> s;
        #pragma unroll
        for (int qb = 0; qb < 16; qb++) {
            if (!(qb & qh)) {
                const int q1 = qb + qh;
                int idx = (((qb & (qh - 1)) * 32 + t) << s);
                float2 c = tw[idx];
                float ur = Rr[qb], ui = Ri[qb];
                float vr = Rr[q1], vi = Ri[q1];
                float dr = ur - vr, di = ui - vi;
                Rr[qb] = ur + vr;  Ri[qb] = ui + vi;
                Rr[q1] = dr * c.x - di * c.y;
                Ri[q1] = dr * c.y + di * c.x;
            }
        }
    }

    /* stages 4..8: cross-lane via shfl_xor */
    #pragma unroll
    for (int s = 4; s < 9; s++) {
        const int hh = 256 >> s;           /* 16,8,4,2,1 */
        float2 c = tw[(t & (hh - 1)) << s];
        const bool up = (t & hh) != 0;
        #pragma unroll
        for (int q = 0; q < 16; q++) {
            float pr = __shfl_xor_sync(0xffffffffu, Rr[q], hh);
            float pi = __shfl_xor_sync(0xffffffffu, Ri[q], hh);
            if (!up) {
                Rr[q] += pr;  Ri[q] += pi;
            } else {
                float dr = pr - Rr[q], di = pi - Ri[q];
                Rr[q] = dr * c.x - di * c.y;
                Ri[q] = dr * c.y + di * c.x;
            }
        }
    }

    /* dump to padded strip: write index q*33+t -> banks (q+t)%32, conflict-free */
    float* zr = sm + SM_A + w * ZSTRIP;
    float* zi = zr + 528;
    #pragma unroll
    for (int q = 0; q < 16; q++) {
        zr[q * 33 + t] = Rr[q];
        zi[q * 33 + t] = Ri[q];
    }
    __syncwarp();

    /* unpack, lane-major (k = 8t+j) with padded reads: conflict-free LDS */
    {
        float pw0[8], pw1[8];
        #pragma unroll
        for (int j = 0; j < 8; j++) {
            int k  = 8 * t + j;
            int kn = (NFFT - k) & (NFFT - 1);
            int r1 = ZPAD(__brev(k)  >> 23);
            int r2 = ZPAD(__brev(kn) >> 23);
            float z1r = zr[r1], z1i = zi[r1];
            float z2r = zr[r2], z2i = zi[r2];
            float Ar = 0.5f * (z1r + z2r);
            float Ai = 0.5f * (z1i - z2i);
            float Br = 0.5f * (z1i + z2i);
            float Bi = 0.5f * (z2r - z1r);
            pw0[j] = Ar * Ar + Ai * Ai;
            pw1[j] = Br * Br + Bi * Bi;
        }
        float4* p0 = (float4*)(pbuf + (2 * w) * PB_PITCH + 8 * t);
        float4* p1 = (float4*)(pbuf + (2 * w + 1) * PB_PITCH + 8 * t);
        p0[0] = make_float4(pw0[0], pw0[1], pw0[2], pw0[3]);
        p0[1] = make_float4(pw0[4], pw0[5], pw0[6], pw0[7]);
        p1[0] = make_float4(pw1[0], pw1[1], pw1[2], pw1[3]);
        p1[1] = make_float4(pw1[4], pw1[5], pw1[6], pw1[7]);
        if (t == 0) {   /* k = 256: Z[256] real pair */
            float zRr = zr[ZPAD(1)], zRi = zi[ZPAD(1)];
            pbuf[(2 * w) * PB_PITCH + 256]     = zRr * zRr;
            pbuf[(2 * w + 1) * PB_PITCH + 256] = zRi * zRi;
        }
    }

    /* wait for mel tables (block 0,0 released them long ago) */
    if (!tblk && tid == 0) {
        while (atomicAdd(&g_mel_ready, 0) == 0) { }
    }
    __syncthreads();

    /* sparse mel + log: 1280 outputs, variable-length vectorized taps */
    for (int oi = tid; oi < NMELS * FPB; oi += 256) {
        int m    = oi >> 4;
        int tloc = oi & 15;
        int s4   = g_mstart[m];
        int nq   = g_mnq[m];
        const float4* wm = (const float4*)(g_mw + m * WTAPS);
        const float4* pv = (const float4*)(pbuf + tloc * PB_PITCH + s4);
        float acc = 0.0f;
        for (int j = 0; j < nq; j++) {
            float4 f = __ldg(&wm[j]);
            float4 p = pv[j];
            acc += f.x * p.x + f.y * p.y + f.z * p.z + f.w * p.w;
        }
        int tt = tbase + tloc;
        if (tt < T)
            out[((size_t)b * NMELS + m) * Tpad + tt] = __logf(acc + LOG_EPSF);
    }
}

/* ------------------------------------------------------------------ K2:
 * per-(b,m) single-pass masked mean/var normalization, float4, in-place.
 */
__global__ void k_norm(float* __restrict__ out, const int* __restrict__ xn32,
                       int T, int Tpad, size_t mainElems, int rem, int B) {
    __shared__ float rsum[8], rsq[8];

    const int tid  = threadIdx.x;          /* 256 */
    const int lane = tid & 31;
    const int wid  = tid >> 5;
    const int m    = blockIdx.x;
    const int b    = blockIdx.y;

    const int seq = load_seqlen(xn32, b);
    int n = seq;
    if (n < 2) n = 2;
    if (n > T) n = T;

    if (m == 0 && tid == 0 && rem > 0) {
        if (rem == B) {
            out[mainElems + b] = (float)seq;
        } else if (rem == 2 * B) {
            ((long long*)(out + mainElems))[b] = (long long)seq;
        } else if (b == 0) {
            for (int i = 0; i < rem && i < B; i++)
                out[mainElems + i] = (float)load_seqlen(xn32, i);
        }
    }

    float* row = out + ((size_t)b * NMELS + m) * Tpad;
    float4* row4 = (float4*)row;
    const int nq = (n + 3) >> 2;

    float lsum = 0.0f, lsq = 0.0f;
    for (int i4 = tid; i4 < nq; i4 += 256) {
        float4 v = row4[i4];
        int tb = 4 * i4;
        if (tb + 0 < n) { lsum += v.x; lsq += v.x * v.x; }
        if (tb + 1 < n) { lsum += v.y; lsq += v.y * v.y; }
        if (tb + 2 < n) { lsum += v.z; lsq += v.z * v.z; }
        if (tb + 3 < n) { lsum += v.w; lsq += v.w * v.w; }
    }
    #pragma unroll
    for (int o = 16; o > 0; o >>= 1) {
        lsum += __shfl_xor_sync(0xffffffffu, lsum, o);
        lsq  += __shfl_xor_sync(0xffffffffu, lsq, o);
    }
    if (lane == 0) { rsum[wid] = lsum; rsq[wid] = lsq; }
    __syncthreads();
    float s1 = rsum[lane & 7], s2 = rsq[lane & 7];
    #pragma unroll
    for (int o = 4; o > 0; o >>= 1) {
        s1 += __shfl_xor_sync(0xffffffffu, s1, o);
        s2 += __shfl_xor_sync(0xffffffffu, s2, o);
    }
    s1 = __shfl_sync(0xffffffffu, s1, 0);
    s2 = __shfl_sync(0xffffffffu, s2, 0);

    const float fn   = (float)n;
    const float mean = s1 / fn;
    const float var  = (s2 - fn * mean * mean) / (fn - 1.0f);
    const float inv  = 1.0f / (sqrtf(fmaxf(var, 0.0f)) + STD_EPSF);

    const int tq = Tpad >> 2;
    for (int i4 = tid; i4 < tq; i4 += 256) {
        float4 v = row4[i4];
        int tb = 4 * i4;
        float4 o;
        o.x = (tb + 0 < n) ? (v.x - mean) * inv : ((tb + 0 < T) ? 0.0f : BLANKF);
        o.y = (tb + 1 < n) ? (v.y - mean) * inv : ((tb + 1 < T) ? 0.0f : BLANKF);
        o.z = (tb + 2 < n) ? (v.z - mean) * inv : ((tb + 2 < T) ? 0.0f : BLANKF);
        o.w = (tb + 3 < n) ? (v.w - mean) * inv : ((tb + 3 < T) ? 0.0f : BLANKF);
        row4[i4] = o;
    }
}

extern "C" void kernel_launch(void* const* d_in, const int* in_sizes, int n_in,
                              void* d_out, int out_size) {
    const float* x    = (const float*)d_in[0];
    const int*   xn32 = (const int*)d_in[1];
    const float* fb   = (const float*)d_in[2];

    const int B    = in_sizes[1];
    const int L    = in_sizes[0] / B;
    const int T    = L / HOP + 1;
    const int Tpad = ((T + 7) / 8) * 8;

    float* out = (float*)d_out;

    cudaFuncSetAttribute(k_fftmel, cudaFuncAttributeMaxDynamicSharedMemorySize,
                         SMEM_BYTES);

    k_fftmel<<<dim3((T + FPB - 1) / FPB, B), 256, SMEM_BYTES>>>(x, fb, out, L, T, Tpad);

    size_t mainE = (size_t)B * NMELS * Tpad;
    int rem = out_size - (int)mainE;
    k_norm<<<dim3(NMELS, B), 256>>>(out, xn32, T, Tpad, mainE, rem, B);
}